// round 9
// baseline (speedup 1.0000x reference)
#include <cuda_runtime.h>
#include <math.h>

// ---------------------------------------------------------------------------
// Multi-scale region distillation loss — two-pass, locality-optimized.
//
// R9: every prior config (MLP 1..8, occ 47..84%, float4/scalar) capped at
// ~3.5TB/s. Hypothesis: 128B-read-then-64KB-jump per warp kills DRAM row
// locality. New pass1 geometry: block = (<=2048 pixels) x (64 channels),
// 8 px/thread with register accumulators -> warp reads 1KB contiguous per
// tensor per channel step (16 consecutive lines per jump).
// Channel groups (NCG=4) write partial dot/na/nb to slot scratch (no atomics);
// pass2 combines slots, does cosine + class bins + finalize + scratch reset.
// ---------------------------------------------------------------------------

#define NUM_SCALES 4
#define MAXC 32
#define LAB_DIM 512
#define THREADS 256
#define NCG 4                    // channel groups per scale
#define MAXPIX 348160            // supports up to 2x the B=8 pixel count

__device__ float        g_part[NCG * 3 * MAXPIX];   // partial dot/na/nb slots
__device__ double       g_seg[NUM_SCALES * MAXC];
__device__ float        g_cnt[NUM_SCALES * MAXC];
__device__ unsigned int g_blocks_done = 0;

struct ScaleDesc {
    const float* f;
    const float* fo;
    int C;           // channels
    int Cg;          // channels per group (C / NCG)
    int W;           // spatial width (=H)
    int HW;          // H*W
    int pixels;      // B*HW
    int PXB;         // pixels per block chunk = min(HW, 2048)
    int npx;         // pixels per thread = PXB / 256
    int block_base;  // first pass1 block of this scale
    int pix_off;     // global pixel offset of this scale
    int sub;         // LAB_DIM / H
};
struct AllDesc { ScaleDesc s[NUM_SCALES]; };

// ---- pass1 inner loop: NPX pixels/thread, UNR channels per batch ----------
template<int NPX, int UNR>
__device__ __forceinline__ void accum_loop(
    const float* __restrict__ fA, const float* __restrict__ fO,
    int HW, int Cg, float* dot, float* na, float* nb)
{
    #pragma unroll 1
    for (int c = 0; c < Cg; c += UNR) {
        float a[NPX * UNR], o[NPX * UNR];
        #pragma unroll
        for (int u = 0; u < UNR; ++u)
            #pragma unroll
            for (int k = 0; k < NPX; ++k)
                a[u * NPX + k] = fA[(size_t)(c + u) * HW + (k << 8)];
        #pragma unroll
        for (int u = 0; u < UNR; ++u)
            #pragma unroll
            for (int k = 0; k < NPX; ++k)
                o[u * NPX + k] = fO[(size_t)(c + u) * HW + (k << 8)];
        #pragma unroll
        for (int u = 0; u < UNR; ++u)
            #pragma unroll
            for (int k = 0; k < NPX; ++k) {
                const float av = a[u * NPX + k], ov = o[u * NPX + k];
                dot[k] = fmaf(av, ov, dot[k]);
                na[k]  = fmaf(av, av, na[k]);
                nb[k]  = fmaf(ov, ov, nb[k]);
            }
    }
}

__global__ void __launch_bounds__(THREADS, 4)
msrd_pass1(AllDesc d, int NPIX)
{
    int sidx;
    if      ((int)blockIdx.x < d.s[1].block_base) sidx = 0;
    else if ((int)blockIdx.x < d.s[2].block_base) sidx = 1;
    else if ((int)blockIdx.x < d.s[3].block_base) sidx = 2;
    else                                          sidx = 3;
    const ScaleDesc sd = d.s[sidx];

    const int local = (int)blockIdx.x - sd.block_base;
    const int pxb   = local >> 2;            // pixel-chunk index (NCG = 4)
    const int cg    = local & (NCG - 1);     // channel group
    const int t     = (int)threadIdx.x;

    const int px0 = pxb * sd.PXB;            // chunk start (global pixel in scale)
    const int b   = px0 / sd.HW;             // PXB <= HW -> single image per block
    const int p0  = px0 - b * sd.HW;

    const float* __restrict__ fA =
        sd.f  + ((size_t)b * sd.C + (size_t)cg * sd.Cg) * sd.HW + p0 + t;
    const float* __restrict__ fO =
        sd.fo + ((size_t)b * sd.C + (size_t)cg * sd.Cg) * sd.HW + p0 + t;

    float dot[8] = {0,0,0,0,0,0,0,0};
    float na [8] = {0,0,0,0,0,0,0,0};
    float nb [8] = {0,0,0,0,0,0,0,0};

    if      (sd.npx == 8) accum_loop<8,1>(fA, fO, sd.HW, sd.Cg, dot, na, nb);
    else if (sd.npx == 4) accum_loop<4,2>(fA, fO, sd.HW, sd.Cg, dot, na, nb);
    else                  accum_loop<1,4>(fA, fO, sd.HW, sd.Cg, dot, na, nb);

    // write partials to this channel-group's slots (coalesced, no atomics)
    const int gpix0 = sd.pix_off + px0 + t;
    float* __restrict__ pd = g_part + (size_t)(cg * 3 + 0) * NPIX;
    float* __restrict__ pa = g_part + (size_t)(cg * 3 + 1) * NPIX;
    float* __restrict__ pb = g_part + (size_t)(cg * 3 + 2) * NPIX;
    #pragma unroll
    for (int k = 0; k < 8; ++k) {
        if (k < sd.npx) {
            pd[gpix0 + (k << 8)] = dot[k];
            pa[gpix0 + (k << 8)] = na[k];
            pb[gpix0 + (k << 8)] = nb[k];
        }
    }
}

__global__ void __launch_bounds__(THREADS, 8)
msrd_pass2(AllDesc d, int NPIX, const int* __restrict__ lab,
           const int* __restrict__ ncls_p, const int* __restrict__ nold_p,
           float* __restrict__ out)
{
    __shared__ float s_seg[MAXC];
    __shared__ float s_cnt[MAXC];
    __shared__ int   s_is_last;
    if (threadIdx.x < MAXC) { s_seg[threadIdx.x] = 0.f; s_cnt[threadIdx.x] = 0.f; }
    __syncthreads();

    const int i = (int)blockIdx.x * THREADS + (int)threadIdx.x;

    // scale of this block (scale pixel counts are multiples of 256)
    const int i0 = (int)blockIdx.x * THREADS;
    int sidx = 0;
    #pragma unroll
    for (int s = 1; s < NUM_SCALES; ++s)
        if (i0 >= d.s[s].pix_off) sidx = s;
    const ScaleDesc sd = d.s[sidx];

    if (i < NPIX) {
        float dot = 0.f, na = 0.f, nb = 0.f;
        #pragma unroll
        for (int cg = 0; cg < NCG; ++cg) {
            dot += g_part[(size_t)(cg * 3 + 0) * NPIX + i];
            na  += g_part[(size_t)(cg * 3 + 1) * NPIX + i];
            nb  += g_part[(size_t)(cg * 3 + 2) * NPIX + i];
        }
        // reset scratch for the next graph replay
        #pragma unroll
        for (int cg = 0; cg < NCG; ++cg) {
            g_part[(size_t)(cg * 3 + 0) * NPIX + i] = 0.f;
            g_part[(size_t)(cg * 3 + 1) * NPIX + i] = 0.f;
            g_part[(size_t)(cg * 3 + 2) * NPIX + i] = 0.f;
        }

        const float nf  = fmaxf(sqrtf(na), 1e-8f);
        const float nfo = fmaxf(sqrtf(nb), 1e-8f);
        const float sim = dot / (nf * nfo);

        const int P = i - sd.pix_off;
        const int b = P / sd.HW;
        const int p = P - b * sd.HW;
        const int h = p / sd.W;
        const int w = p - h * sd.W;
        const int l = lab[(size_t)b * LAB_DIM * LAB_DIM
                          + (size_t)(h * sd.sub) * LAB_DIM + (size_t)w * sd.sub];
        if (l >= 0 && l < MAXC) {
            atomicAdd(&s_seg[l], sim);
            atomicAdd(&s_cnt[l], 1.0f);
        }
    }

    __syncthreads();
    if (threadIdx.x < MAXC) {
        const float cs = s_cnt[threadIdx.x];
        if (cs != 0.0f) {
            atomicAdd(&g_seg[sidx * MAXC + threadIdx.x], (double)s_seg[threadIdx.x]);
            atomicAdd(&g_cnt[sidx * MAXC + threadIdx.x], cs);
        }
    }

    // ---- last-block finalize ----
    __syncthreads();
    if (threadIdx.x == 0) {
        __threadfence();
        const unsigned int done = atomicAdd(&g_blocks_done, 1u);
        s_is_last = (done == gridDim.x - 1) ? 1 : 0;
    }
    __syncthreads();

    if (s_is_last) {
        __threadfence();
        if (threadIdx.x == 0) {
            const int nc = ncls_p ? *ncls_p : 21;
            const int no = nold_p ? *nold_p : 15;
            const double wts[NUM_SCALES] = {1.0, 2.0, 3.0, 4.0};
            double loss = 0.0;
            for (int s = 0; s < NUM_SCALES; ++s) {
                for (int cls = 0; cls < nc && cls < MAXC; ++cls) {
                    const float cnt = g_cnt[s * MAXC + cls];
                    if (cnt > 0.0f) {
                        const double mean = g_seg[s * MAXC + cls] / (double)cnt;
                        double factor;
                        if (cls == 0)        factor = (double)no / (double)nc;
                        else if (cls <= no)  factor = 1.0;
                        else                 factor = 0.0;
                        loss += wts[s] * factor * (1.0 - mean);
                    }
                }
            }
            *out = (float)loss;
        }
        __syncthreads();   // finalize read before bin reset
        if (threadIdx.x == 0) g_blocks_done = 0;
        if (threadIdx.x < NUM_SCALES * MAXC / 2) {
            const int i0r = threadIdx.x * 2;
            g_seg[i0r] = 0.0;  g_seg[i0r + 1] = 0.0;
            g_cnt[i0r] = 0.0f; g_cnt[i0r + 1] = 0.0f;
        }
    }
}

extern "C" void kernel_launch(void* const* d_in, const int* in_sizes, int n_in,
                              void* d_out, int out_size)
{
    const int* lab = (const int*)d_in[0];
    const int B = in_sizes[0] / (LAB_DIM * LAB_DIM);

    // ---- identify feature buffers by size (order-agnostic) ----
    const float* fbuf[NUM_SCALES]  = {nullptr, nullptr, nullptr, nullptr};
    const float* fobuf[NUM_SCALES] = {nullptr, nullptr, nullptr, nullptr};
    long         szs[NUM_SCALES]   = {0, 0, 0, 0};
    int ns = 0;
    const int* scalar_ptrs[2] = {nullptr, nullptr};
    int nscalar = 0;

    for (int i = 1; i < n_in; ++i) {
        const long sz = in_sizes[i];
        if (sz <= 1) {
            if (nscalar < 2) scalar_ptrs[nscalar++] = (const int*)d_in[i];
            continue;
        }
        int j = 0;
        while (j < ns && szs[j] != sz) ++j;
        if (j == ns && ns < NUM_SCALES) {
            szs[ns] = sz; fbuf[ns] = (const float*)d_in[i]; ++ns;
        } else if (j < ns) {
            fobuf[j] = (const float*)d_in[i];
        }
    }
    for (int i = 0; i < ns; ++i)
        for (int j = i + 1; j < ns; ++j)
            if (szs[j] > szs[i]) {
                long ts = szs[i]; szs[i] = szs[j]; szs[j] = ts;
                const float* tf = fbuf[i]; fbuf[i] = fbuf[j]; fbuf[j] = tf;
                const float* to = fobuf[i]; fobuf[i] = fobuf[j]; fobuf[j] = to;
            }

    // ---- per-scale descriptors ----
    AllDesc ad;
    int block_base = 0;
    int pix_off = 0;
    for (int s = 0; s < NUM_SCALES; ++s) {
        const int HW_dim = 128 >> s;             // 128,64,32,16
        const int HW     = HW_dim * HW_dim;
        const int C      = (int)(szs[s] / ((long)B * HW));
        const int pixels = B * HW;
        const int PXB    = (HW < 2048) ? HW : 2048;
        const int npx    = PXB / THREADS;
        const int nblk   = (pixels / PXB) * NCG;

        ad.s[s].f          = fbuf[s];
        ad.s[s].fo         = fobuf[s];
        ad.s[s].C          = C;
        ad.s[s].Cg         = C / NCG;
        ad.s[s].W          = HW_dim;
        ad.s[s].HW         = HW;
        ad.s[s].pixels     = pixels;
        ad.s[s].PXB        = PXB;
        ad.s[s].npx        = npx;
        ad.s[s].block_base = block_base;
        ad.s[s].pix_off    = pix_off;
        ad.s[s].sub        = LAB_DIM / HW_dim;
        block_base += nblk;
        pix_off    += pixels;
    }
    const int NPIX = pix_off;

    msrd_pass1<<<block_base, THREADS>>>(ad, NPIX);
    const int p2_blocks = (NPIX + THREADS - 1) / THREADS;
    msrd_pass2<<<p2_blocks, THREADS>>>(ad, NPIX, lab,
                                       scalar_ptrs[0], scalar_ptrs[1],
                                       (float*)d_out);
}

// round 10
// speedup vs baseline: 1.0134x; 1.0134x over previous
#include <cuda_runtime.h>
#include <math.h>

// ---------------------------------------------------------------------------
// Multi-scale region distillation loss — two-pass, locality-optimized.
//
// pass1 (UNCHANGED from R9 — measured ~6.8TB/s): block = (<=2048 px) x (64 ch),
// 8 px/thread register accumulators; warp reads 1KB contiguous per tensor per
// channel step. Channel groups (NCG=4) store partial dot/na/nb to slot scratch.
//
// pass2 (R10 rewrite): float4 loads (4 px/thread), NO scratch reset (pass1
// fully overwrites g_part every replay), class bins + last-block finalize.
// R9's pass2 wasted 16.7MB of stores on a pointless reset and ran scalar.
// ---------------------------------------------------------------------------

#define NUM_SCALES 4
#define MAXC 32
#define LAB_DIM 512
#define THREADS 256
#define NCG 4                    // channel groups per scale
#define MAXPIX 348160

__device__ float        g_part[NCG * 3 * MAXPIX];   // partial dot/na/nb slots
__device__ double       g_seg[NUM_SCALES * MAXC];
__device__ float        g_cnt[NUM_SCALES * MAXC];
__device__ unsigned int g_blocks_done = 0;

struct ScaleDesc {
    const float* f;
    const float* fo;
    int C;           // channels
    int Cg;          // channels per group (C / NCG)
    int W;           // spatial width (=H)
    int HW;          // H*W
    int pixels;      // B*HW
    int PXB;         // pixels per block chunk = min(HW, 2048)
    int npx;         // pixels per thread = PXB / 256
    int block_base;  // first pass1 block of this scale
    int pix_off;     // global pixel offset of this scale
    int sub;         // LAB_DIM / H
};
struct AllDesc { ScaleDesc s[NUM_SCALES]; };

// ---- pass1 inner loop: NPX pixels/thread, UNR channels per batch ----------
template<int NPX, int UNR>
__device__ __forceinline__ void accum_loop(
    const float* __restrict__ fA, const float* __restrict__ fO,
    int HW, int Cg, float* dot, float* na, float* nb)
{
    #pragma unroll 1
    for (int c = 0; c < Cg; c += UNR) {
        float a[NPX * UNR], o[NPX * UNR];
        #pragma unroll
        for (int u = 0; u < UNR; ++u)
            #pragma unroll
            for (int k = 0; k < NPX; ++k)
                a[u * NPX + k] = fA[(size_t)(c + u) * HW + (k << 8)];
        #pragma unroll
        for (int u = 0; u < UNR; ++u)
            #pragma unroll
            for (int k = 0; k < NPX; ++k)
                o[u * NPX + k] = fO[(size_t)(c + u) * HW + (k << 8)];
        #pragma unroll
        for (int u = 0; u < UNR; ++u)
            #pragma unroll
            for (int k = 0; k < NPX; ++k) {
                const float av = a[u * NPX + k], ov = o[u * NPX + k];
                dot[k] = fmaf(av, ov, dot[k]);
                na[k]  = fmaf(av, av, na[k]);
                nb[k]  = fmaf(ov, ov, nb[k]);
            }
    }
}

__global__ void __launch_bounds__(THREADS, 4)
msrd_pass1(AllDesc d, int NPIX)
{
    int sidx;
    if      ((int)blockIdx.x < d.s[1].block_base) sidx = 0;
    else if ((int)blockIdx.x < d.s[2].block_base) sidx = 1;
    else if ((int)blockIdx.x < d.s[3].block_base) sidx = 2;
    else                                          sidx = 3;
    const ScaleDesc sd = d.s[sidx];

    const int local = (int)blockIdx.x - sd.block_base;
    const int pxb   = local >> 2;            // pixel-chunk index (NCG = 4)
    const int cg    = local & (NCG - 1);     // channel group
    const int t     = (int)threadIdx.x;

    const int px0 = pxb * sd.PXB;            // chunk start (global pixel in scale)
    const int b   = px0 / sd.HW;             // PXB <= HW -> single image per block
    const int p0  = px0 - b * sd.HW;

    const float* __restrict__ fA =
        sd.f  + ((size_t)b * sd.C + (size_t)cg * sd.Cg) * sd.HW + p0 + t;
    const float* __restrict__ fO =
        sd.fo + ((size_t)b * sd.C + (size_t)cg * sd.Cg) * sd.HW + p0 + t;

    float dot[8] = {0,0,0,0,0,0,0,0};
    float na [8] = {0,0,0,0,0,0,0,0};
    float nb [8] = {0,0,0,0,0,0,0,0};

    if      (sd.npx == 8) accum_loop<8,1>(fA, fO, sd.HW, sd.Cg, dot, na, nb);
    else if (sd.npx == 4) accum_loop<4,2>(fA, fO, sd.HW, sd.Cg, dot, na, nb);
    else                  accum_loop<1,4>(fA, fO, sd.HW, sd.Cg, dot, na, nb);

    // write partials to this channel-group's slots (coalesced, no atomics)
    const int gpix0 = sd.pix_off + px0 + t;
    float* __restrict__ pd = g_part + (size_t)(cg * 3 + 0) * NPIX;
    float* __restrict__ pa = g_part + (size_t)(cg * 3 + 1) * NPIX;
    float* __restrict__ pb = g_part + (size_t)(cg * 3 + 2) * NPIX;
    #pragma unroll
    for (int k = 0; k < 8; ++k) {
        if (k < sd.npx) {
            pd[gpix0 + (k << 8)] = dot[k];
            pa[gpix0 + (k << 8)] = na[k];
            pb[gpix0 + (k << 8)] = nb[k];
        }
    }
}

// pass2: 1 thread = 4 pixels (float4). NPIX is a multiple of 1024, and every
// scale's pix_off is 1024-aligned, so a block never straddles scales.
__global__ void __launch_bounds__(THREADS, 4)
msrd_pass2(AllDesc d, int NPIX, const int* __restrict__ lab,
           const int* __restrict__ ncls_p, const int* __restrict__ nold_p,
           float* __restrict__ out)
{
    __shared__ float s_seg[MAXC];
    __shared__ float s_cnt[MAXC];
    __shared__ int   s_is_last;
    if (threadIdx.x < MAXC) { s_seg[threadIdx.x] = 0.f; s_cnt[threadIdx.x] = 0.f; }
    __syncthreads();

    const int pix0 = (int)blockIdx.x * (THREADS * 4);
    int sidx = 0;
    #pragma unroll
    for (int s = 1; s < NUM_SCALES; ++s)
        if (pix0 >= d.s[s].pix_off) sidx = s;
    const ScaleDesc sd = d.s[sidx];

    const int i = pix0 + (int)threadIdx.x * 4;   // first of 4 pixels
    if (i < NPIX) {
        float4 dot = make_float4(0.f, 0.f, 0.f, 0.f);
        float4 na  = make_float4(0.f, 0.f, 0.f, 0.f);
        float4 nb  = make_float4(0.f, 0.f, 0.f, 0.f);
        #pragma unroll
        for (int cg = 0; cg < NCG; ++cg) {
            const float4 pd = *(const float4*)(g_part + (size_t)(cg * 3 + 0) * NPIX + i);
            const float4 pa = *(const float4*)(g_part + (size_t)(cg * 3 + 1) * NPIX + i);
            const float4 pb = *(const float4*)(g_part + (size_t)(cg * 3 + 2) * NPIX + i);
            dot.x += pd.x; dot.y += pd.y; dot.z += pd.z; dot.w += pd.w;
            na.x  += pa.x; na.y  += pa.y; na.z  += pa.z; na.w  += pa.w;
            nb.x  += pb.x; nb.y  += pb.y; nb.z  += pb.z; nb.w  += pb.w;
        }

        const int P = i - sd.pix_off;      // 4 consecutive pixels, same row
        const int b = P / sd.HW;
        const int p = P - b * sd.HW;
        const int h = p / sd.W;
        const int w = p - h * sd.W;
        const int* __restrict__ lrow =
            lab + (size_t)b * LAB_DIM * LAB_DIM + (size_t)(h * sd.sub) * LAB_DIM;

        const float dots[4] = {dot.x, dot.y, dot.z, dot.w};
        const float nas [4] = {na.x,  na.y,  na.z,  na.w };
        const float nbs [4] = {nb.x,  nb.y,  nb.z,  nb.w };

        #pragma unroll
        for (int k = 0; k < 4; ++k) {
            const float nf  = fmaxf(sqrtf(nas[k]), 1e-8f);
            const float nfo = fmaxf(sqrtf(nbs[k]), 1e-8f);
            const float sim = dots[k] / (nf * nfo);
            const int   l   = lrow[(w + k) * sd.sub];
            if (l >= 0 && l < MAXC) {
                atomicAdd(&s_seg[l], sim);
                atomicAdd(&s_cnt[l], 1.0f);
            }
        }
    }

    __syncthreads();
    if (threadIdx.x < MAXC) {
        const float cs = s_cnt[threadIdx.x];
        if (cs != 0.0f) {
            atomicAdd(&g_seg[sidx * MAXC + threadIdx.x], (double)s_seg[threadIdx.x]);
            atomicAdd(&g_cnt[sidx * MAXC + threadIdx.x], cs);
        }
    }

    // ---- last-block finalize ----
    __syncthreads();
    if (threadIdx.x == 0) {
        __threadfence();
        const unsigned int done = atomicAdd(&g_blocks_done, 1u);
        s_is_last = (done == gridDim.x - 1) ? 1 : 0;
    }
    __syncthreads();

    if (s_is_last) {
        __threadfence();
        if (threadIdx.x == 0) {
            const int nc = ncls_p ? *ncls_p : 21;
            const int no = nold_p ? *nold_p : 15;
            const double wts[NUM_SCALES] = {1.0, 2.0, 3.0, 4.0};
            double loss = 0.0;
            for (int s = 0; s < NUM_SCALES; ++s) {
                for (int cls = 0; cls < nc && cls < MAXC; ++cls) {
                    const float cnt = g_cnt[s * MAXC + cls];
                    if (cnt > 0.0f) {
                        const double mean = g_seg[s * MAXC + cls] / (double)cnt;
                        double factor;
                        if (cls == 0)        factor = (double)no / (double)nc;
                        else if (cls <= no)  factor = 1.0;
                        else                 factor = 0.0;
                        loss += wts[s] * factor * (1.0 - mean);
                    }
                }
            }
            *out = (float)loss;
        }
        __syncthreads();   // finalize read before bin reset
        if (threadIdx.x == 0) g_blocks_done = 0;
        if (threadIdx.x < NUM_SCALES * MAXC / 2) {
            const int r = threadIdx.x * 2;
            g_seg[r] = 0.0;  g_seg[r + 1] = 0.0;
            g_cnt[r] = 0.0f; g_cnt[r + 1] = 0.0f;
        }
        // NOTE: g_part needs no reset — pass1 fully overwrites it each replay.
    }
}

extern "C" void kernel_launch(void* const* d_in, const int* in_sizes, int n_in,
                              void* d_out, int out_size)
{
    const int* lab = (const int*)d_in[0];
    const int B = in_sizes[0] / (LAB_DIM * LAB_DIM);

    // ---- identify feature buffers by size (order-agnostic) ----
    const float* fbuf[NUM_SCALES]  = {nullptr, nullptr, nullptr, nullptr};
    const float* fobuf[NUM_SCALES] = {nullptr, nullptr, nullptr, nullptr};
    long         szs[NUM_SCALES]   = {0, 0, 0, 0};
    int ns = 0;
    const int* scalar_ptrs[2] = {nullptr, nullptr};
    int nscalar = 0;

    for (int i = 1; i < n_in; ++i) {
        const long sz = in_sizes[i];
        if (sz <= 1) {
            if (nscalar < 2) scalar_ptrs[nscalar++] = (const int*)d_in[i];
            continue;
        }
        int j = 0;
        while (j < ns && szs[j] != sz) ++j;
        if (j == ns && ns < NUM_SCALES) {
            szs[ns] = sz; fbuf[ns] = (const float*)d_in[i]; ++ns;
        } else if (j < ns) {
            fobuf[j] = (const float*)d_in[i];
        }
    }
    for (int i = 0; i < ns; ++i)
        for (int j = i + 1; j < ns; ++j)
            if (szs[j] > szs[i]) {
                long ts = szs[i]; szs[i] = szs[j]; szs[j] = ts;
                const float* tf = fbuf[i]; fbuf[i] = fbuf[j]; fbuf[j] = tf;
                const float* to = fobuf[i]; fobuf[i] = fobuf[j]; fobuf[j] = to;
            }

    // ---- per-scale descriptors ----
    AllDesc ad;
    int block_base = 0;
    int pix_off = 0;
    for (int s = 0; s < NUM_SCALES; ++s) {
        const int HW_dim = 128 >> s;             // 128,64,32,16
        const int HW     = HW_dim * HW_dim;
        const int C      = (int)(szs[s] / ((long)B * HW));
        const int pixels = B * HW;
        const int PXB    = (HW < 2048) ? HW : 2048;
        const int npx    = PXB / THREADS;
        const int nblk   = (pixels / PXB) * NCG;

        ad.s[s].f          = fbuf[s];
        ad.s[s].fo         = fobuf[s];
        ad.s[s].C          = C;
        ad.s[s].Cg         = C / NCG;
        ad.s[s].W          = HW_dim;
        ad.s[s].HW         = HW;
        ad.s[s].pixels     = pixels;
        ad.s[s].PXB        = PXB;
        ad.s[s].npx        = npx;
        ad.s[s].block_base = block_base;
        ad.s[s].pix_off    = pix_off;
        ad.s[s].sub        = LAB_DIM / HW_dim;
        block_base += nblk;
        pix_off    += pixels;
    }
    const int NPIX = pix_off;

    msrd_pass1<<<block_base, THREADS>>>(ad, NPIX);
    const int p2_blocks = (NPIX + THREADS * 4 - 1) / (THREADS * 4);
    msrd_pass2<<<p2_blocks, THREADS>>>(ad, NPIX, lab,
                                       scalar_ptrs[0], scalar_ptrs[1],
                                       (float*)d_out);
}